// round 12
// baseline (speedup 1.0000x reference)
#include <cuda_runtime.h>

// Problem constants
#define S2       100                   // S*S
#define NCH      24                    // 3*B + C
#define NCLS     21
#define BATCHN   32768
#define NCELLS   (BATCHN * S2)         // 3,276,800
#define GRID     3200
#define WPB      8                     // warps per block
#define WARPS_TOTAL (GRID * WPB)       // 25600
#define NCHUNKS  (NCELLS / 32)         // 102,400 (32 cells per warp-chunk)
#define CPW      (NCHUNKS / WARPS_TOTAL) // 4 chunks per warp
#define WSTRIDE  33                    // per-warp smem row stride (floats)
#define WSLICE   (NCH * WSTRIDE)       // 792 floats per warp slice

// Loss weights
#define LAMBDA_COORD 10.0
#define LAMBDA_NOOBJ 1.0
#define LAMBDA_CLASS 0.5

// log(w / SCALE) = log(w * INV_SCALE), SCALE = 6.5131/40
__device__ __constant__ float INV_SCALE = 40.0f / 6.5131f;

// Cross-block accumulators [xy, wh, obj, noobj, class], each on its own
// 128B line. Zero-initialized at module load; the finalizing block resets
// them after reading, so every launch / graph replay starts from zero.
#define ACC_STRIDE 16   // doubles per slot (128 B)
__device__ double g_acc[5 * ACC_STRIDE];     // static-init 0.0
__device__ unsigned int g_done;              // static-init 0

__device__ __forceinline__ float warp_reduce(float v) {
#pragma unroll
    for (int o = 16; o > 0; o >>= 1)
        v += __shfl_down_sync(0xffffffffu, v, o);
    return v;
}

// min 5 blocks/SM -> regs capped at 48 -> 40 resident warps/SM
__global__ __launch_bounds__(256, 5)
void loss_kernel(const float4* __restrict__ pred4,   // NCELLS*6 float4
                 const float4* __restrict__ tgt4,    // NCELLS float4
                 float* __restrict__ out) {
    // Per-warp private staging slices: no block-wide barriers in the mainloop.
    __shared__ float s[WPB * WSLICE];

    const int tid  = threadIdx.x;
    const int lane = tid & 31;
    const int wid  = tid >> 5;
    float* ss = &s[wid * WSLICE];     // this warp's slice, stride WSTRIDE

    float lxy = 0.f, lwh = 0.f, lobj = 0.f, lnoobj = 0.f, lcls = 0.f;

    // ---- prefetch chunk 0 (32 cells) into registers ----
    int chunk = blockIdx.x * WPB + wid;
    float4 t = tgt4[chunk * 32 + lane];
    float4 v[6];
    {
        const float4* pb = pred4 + (size_t)chunk * (32 * 6);
#pragma unroll
        for (int k = 0; k < 6; k++) v[k] = pb[lane + k * 32];
    }

#pragma unroll 1
    for (int it = 0; it < CPW; it++) {
        // ---- store prefetched chunk to warp slice (channel-major) ----
#pragma unroll
        for (int k = 0; k < 6; k++) {
            const int f = lane + k * 32;           // local float4 index
            const int c = f / 6;                   // cell within chunk [0,32)
            const int j = f - 6 * c;               // float4 slot in cell
            const int ch = 4 * j;
            ss[(ch + 0) * WSTRIDE + c] = v[k].x;
            ss[(ch + 1) * WSTRIDE + c] = v[k].y;
            ss[(ch + 2) * WSTRIDE + c] = v[k].z;
            ss[(ch + 3) * WSTRIDE + c] = v[k].w;
        }
        const float4 tc = t;   // current chunk's target (this lane's cell)
        __syncwarp();

        // ---- issue next chunk's loads NOW; they fly during compute ----
        const int nchunk = chunk + WARPS_TOTAL;
        if (it + 1 < CPW) {
            t = tgt4[nchunk * 32 + lane];
            const float4* pb = pred4 + (size_t)nchunk * (32 * 6);
#pragma unroll
            for (int k = 0; k < 6; k++) v[k] = pb[lane + k * 32];
        }
        chunk = nchunk;

        // ---- per-cell loss; slice reads conflict-free (stride 33) ----
        const float conf_t = tc.z;  // 0 or 1
        const float sig_conf = 1.f / (1.f + __expf(-ss[2 * WSTRIDE + lane]));

        if (conf_t > 0.f) {
            const float dc = sig_conf - conf_t;
            lobj += dc * dc;

            const float sig_x = 1.f / (1.f + __expf(-ss[0 * WSTRIDE + lane]));
            const float dx = sig_x - tc.x;
            lxy += dx * dx;

            const float dw = ss[1 * WSTRIDE + lane] - __logf(tc.y * INV_SCALE);
            lwh += dw * dw;

            if (tc.w > 0.f) {
                float esum = 0.f, wsum = 0.f;
#pragma unroll
                for (int c = 0; c < NCLS; c++) {
                    const float e = __expf(ss[(3 + c) * WSTRIDE + lane]);
                    esum += e;
                    wsum += e * (1.0f + 0.5f * (float)c);
                }
                const float pred_mass = wsum / esum;
                const float diff = 10.f * (pred_mass + 1.f) / (tc.w + 1.f) - 10.f;
                const float ad = fabsf(diff);
                lcls += (ad < 1.f) ? 0.5f * diff * diff : (ad - 0.5f);
            }
        } else {
            lnoobj += sig_conf * sig_conf;   // target conf == 0
        }
        __syncwarp();   // slice consumed; next iteration overwrites
    }

    // ---- block reduction: warp shuffle -> smem -> warp0 -> double atomics ----
    __shared__ float r[5][WPB];

    lxy    = warp_reduce(lxy);
    lwh    = warp_reduce(lwh);
    lobj   = warp_reduce(lobj);
    lnoobj = warp_reduce(lnoobj);
    lcls   = warp_reduce(lcls);

    if (lane == 0) {
        r[0][wid] = lxy;  r[1][wid] = lwh;  r[2][wid] = lobj;
        r[3][wid] = lnoobj;  r[4][wid] = lcls;
    }
    __syncthreads();

    if (wid == 0) {
        float a0 = (lane < WPB) ? r[0][lane] : 0.f;
        float a1 = (lane < WPB) ? r[1][lane] : 0.f;
        float a2 = (lane < WPB) ? r[2][lane] : 0.f;
        float a3 = (lane < WPB) ? r[3][lane] : 0.f;
        float a4 = (lane < WPB) ? r[4][lane] : 0.f;
        a0 = warp_reduce(a0);
        a1 = warp_reduce(a1);
        a2 = warp_reduce(a2);
        a3 = warp_reduce(a3);
        a4 = warp_reduce(a4);

        if (lane == 0) {
            atomicAdd(&g_acc[0 * ACC_STRIDE], (double)a0);
            atomicAdd(&g_acc[1 * ACC_STRIDE], (double)a1);
            atomicAdd(&g_acc[2 * ACC_STRIDE], (double)a2);
            atomicAdd(&g_acc[3 * ACC_STRIDE], (double)a3);
            atomicAdd(&g_acc[4 * ACC_STRIDE], (double)a4);

            // ---- last-block-done finalize ----
            __threadfence();
            const unsigned int prev = atomicAdd(&g_done, 1u);
            if (prev == GRID - 1) {
                const double xy  = atomicAdd(&g_acc[0 * ACC_STRIDE], 0.0);
                const double wh  = atomicAdd(&g_acc[1 * ACC_STRIDE], 0.0);
                const double obj = atomicAdd(&g_acc[2 * ACC_STRIDE], 0.0);
                const double nob = atomicAdd(&g_acc[3 * ACC_STRIDE], 0.0);
                const double cls = atomicAdd(&g_acc[4 * ACC_STRIDE], 0.0);
                const double total = LAMBDA_COORD * (xy + wh) + obj
                                   + LAMBDA_NOOBJ * nob + LAMBDA_CLASS * cls;
                const double inv_bs = 1.0 / (double)BATCHN;
                out[0] = (float)(xy  * inv_bs);
                out[1] = (float)(wh  * inv_bs);
                out[2] = (float)(obj * inv_bs);
                out[3] = (float)(nob * inv_bs);
                out[4] = (float)(cls * inv_bs);
                out[5] = (float)(total * inv_bs);
                // Reset state for the next launch / graph replay.
                g_acc[0 * ACC_STRIDE] = 0.0;
                g_acc[1 * ACC_STRIDE] = 0.0;
                g_acc[2 * ACC_STRIDE] = 0.0;
                g_acc[3 * ACC_STRIDE] = 0.0;
                g_acc[4 * ACC_STRIDE] = 0.0;
                __threadfence();
                g_done = 0u;
            }
        }
    }
}

extern "C" void kernel_launch(void* const* d_in, const int* in_sizes, int n_in,
                              void* d_out, int out_size) {
    // pred is the big input (NCELLS*24 floats); target is NCELLS*4
    const float* pred = (const float*)d_in[0];
    const float* tgt  = (const float*)d_in[1];
    if (n_in >= 2 && in_sizes[0] < in_sizes[1]) {
        pred = (const float*)d_in[1];
        tgt  = (const float*)d_in[0];
    }

    loss_kernel<<<GRID, 256>>>(reinterpret_cast<const float4*>(pred),
                               reinterpret_cast<const float4*>(tgt),
                               (float*)d_out);
}

// round 16
// speedup vs baseline: 1.2361x; 1.2361x over previous
#include <cuda_runtime.h>

// Problem constants
#define S2       100                   // S*S
#define NCH      24                    // 3*B + C
#define NCLS     21
#define BATCHN   32768
#define NCELLS   (BATCHN * S2)         // 3,276,800
#define GRID     3200
#define WPB      8                     // warps per block
#define WARPS_TOTAL (GRID * WPB)       // 25600
#define CHUNK    16                    // cells per warp-iteration (2 lanes/cell)
#define NCHUNKS  (NCELLS / CHUNK)      // 204,800
#define CPW      (NCHUNKS / WARPS_TOTAL) // 8 chunks per warp
#define WSTRIDE  17                    // per-warp smem row stride (floats)
#define WSLICE   (NCH * WSTRIDE)       // 408 floats per warp slice

// Loss weights
#define LAMBDA_COORD 10.0
#define LAMBDA_NOOBJ 1.0
#define LAMBDA_CLASS 0.5

// log(w / SCALE) = log(w * INV_SCALE), SCALE = 6.5131/40
__device__ __constant__ float INV_SCALE = 40.0f / 6.5131f;

// Cross-block accumulators [xy, wh, obj, noobj, class], each on its own
// 128B line. Zero-initialized at module load; the finalizing block resets
// them after reading, so every launch / graph replay starts from zero.
#define ACC_STRIDE 16   // doubles per slot (128 B)
__device__ double g_acc[5 * ACC_STRIDE];     // static-init 0.0
__device__ unsigned int g_done;              // static-init 0

__device__ __forceinline__ float warp_reduce(float v) {
#pragma unroll
    for (int o = 16; o > 0; o >>= 1)
        v += __shfl_down_sync(0xffffffffu, v, o);
    return v;
}

// 5 blocks/SM (cap 48 regs); true live state ~40 regs after halving prefetch.
__global__ __launch_bounds__(256, 5)
void loss_kernel(const float4* __restrict__ pred4,   // NCELLS*6 float4
                 const float4* __restrict__ tgt4,    // NCELLS float4
                 float* __restrict__ out) {
    // Per-warp private staging slices; no block-wide barriers in the mainloop.
    __shared__ float s[WPB * WSLICE];

    const int tid  = threadIdx.x;
    const int lane = tid & 31;
    const int wid  = tid >> 5;
    const int cell = lane >> 1;        // pair-shared cell [0,16)
    const int sub  = lane & 1;         // role within the pair
    float* ss = &s[wid * WSLICE];      // this warp's slice, stride WSTRIDE

    float lxy = 0.f, lwh = 0.f, lobj = 0.f, lnoobj = 0.f, lcls = 0.f;

    // ---- prefetch chunk 0 (16 cells = 96 float4) into registers ----
    int chunk = blockIdx.x * WPB + wid;
    float4 t = tgt4[chunk * CHUNK + cell];     // pair lanes load same addr (bcast)
    float4 v[3];
    {
        const float4* pb = pred4 + (size_t)chunk * (CHUNK * 6);
#pragma unroll
        for (int k = 0; k < 3; k++) v[k] = pb[lane + k * 32];
    }

#pragma unroll 1
    for (int it = 0; it < CPW; it++) {
        // ---- store prefetched chunk to warp slice (channel-major) ----
#pragma unroll
        for (int k = 0; k < 3; k++) {
            const int f = lane + k * 32;           // local float4 index [0,96)
            const int c = f / 6;                   // cell within chunk [0,16)
            const int j = f - 6 * c;               // float4 slot in cell
            const int ch = 4 * j;
            ss[(ch + 0) * WSTRIDE + c] = v[k].x;
            ss[(ch + 1) * WSTRIDE + c] = v[k].y;
            ss[(ch + 2) * WSTRIDE + c] = v[k].z;
            ss[(ch + 3) * WSTRIDE + c] = v[k].w;
        }
        const float4 tc = t;   // current chunk's target (this pair's cell)
        __syncwarp();

        // ---- issue next chunk's loads NOW; they fly during compute ----
        const int nchunk = chunk + WARPS_TOTAL;
        if (it + 1 < CPW) {
            t = tgt4[nchunk * CHUNK + cell];
            const float4* pb = pred4 + (size_t)nchunk * (CHUNK * 6);
#pragma unroll
            for (int k = 0; k < 3; k++) v[k] = pb[lane + k * 32];
        }
        chunk = nchunk;

        // ---- per-cell loss; pair lanes share one cell ----
        const bool coord = tc.z > 0.f;   // 0 or 1, identical across the pair

        if (sub == 0) {
            const float sig_conf = 1.f / (1.f + __expf(-ss[2 * WSTRIDE + cell]));
            if (coord) {
                const float dc = sig_conf - tc.z;
                lobj += dc * dc;

                const float sig_x = 1.f / (1.f + __expf(-ss[0 * WSTRIDE + cell]));
                const float dx = sig_x - tc.x;
                lxy += dx * dx;

                const float dw = ss[1 * WSTRIDE + cell] - __logf(tc.y * INV_SCALE);
                lwh += dw * dw;
            } else {
                lnoobj += sig_conf * sig_conf;
            }
        }

        // ---- class / mass softmax split across the lane pair ----
        const bool clsact = coord && (tc.w > 0.f);   // same for both pair lanes
        const unsigned clsmask = __ballot_sync(0xffffffffu, clsact);
        if (clsact) {
            float esum = 0.f, wsum = 0.f;
#pragma unroll
            for (int i = 0; i < 11; i++) {
                const int c2 = 2 * i + sub;          // sub0: 0,2,..20  sub1: 1,..19
                if (c2 < NCLS) {
                    const float e = __expf(ss[(3 + c2) * WSTRIDE + cell]);
                    esum += e;
                    wsum += e * (1.0f + 0.5f * (float)c2);
                }
            }
            // combine pair halves (partner lane guaranteed in clsmask)
            esum += __shfl_xor_sync(clsmask, esum, 1);
            wsum += __shfl_xor_sync(clsmask, wsum, 1);
            if (sub == 0) {
                const float pred_mass = wsum / esum;
                const float diff = 10.f * (pred_mass + 1.f) / (tc.w + 1.f) - 10.f;
                const float ad = fabsf(diff);
                lcls += (ad < 1.f) ? 0.5f * diff * diff : (ad - 0.5f);
            }
        }
        __syncwarp();   // slice consumed; next iteration overwrites
    }

    // ---- block reduction: warp shuffle -> smem -> warp0 -> double atomics ----
    __shared__ float r[5][WPB];

    lxy    = warp_reduce(lxy);
    lwh    = warp_reduce(lwh);
    lobj   = warp_reduce(lobj);
    lnoobj = warp_reduce(lnoobj);
    lcls   = warp_reduce(lcls);

    if (lane == 0) {
        r[0][wid] = lxy;  r[1][wid] = lwh;  r[2][wid] = lobj;
        r[3][wid] = lnoobj;  r[4][wid] = lcls;
    }
    __syncthreads();

    if (wid == 0) {
        float a0 = (lane < WPB) ? r[0][lane] : 0.f;
        float a1 = (lane < WPB) ? r[1][lane] : 0.f;
        float a2 = (lane < WPB) ? r[2][lane] : 0.f;
        float a3 = (lane < WPB) ? r[3][lane] : 0.f;
        float a4 = (lane < WPB) ? r[4][lane] : 0.f;
        a0 = warp_reduce(a0);
        a1 = warp_reduce(a1);
        a2 = warp_reduce(a2);
        a3 = warp_reduce(a3);
        a4 = warp_reduce(a4);

        if (lane == 0) {
            atomicAdd(&g_acc[0 * ACC_STRIDE], (double)a0);
            atomicAdd(&g_acc[1 * ACC_STRIDE], (double)a1);
            atomicAdd(&g_acc[2 * ACC_STRIDE], (double)a2);
            atomicAdd(&g_acc[3 * ACC_STRIDE], (double)a3);
            atomicAdd(&g_acc[4 * ACC_STRIDE], (double)a4);

            // ---- last-block-done finalize ----
            __threadfence();
            const unsigned int prev = atomicAdd(&g_done, 1u);
            if (prev == GRID - 1) {
                const double xy  = atomicAdd(&g_acc[0 * ACC_STRIDE], 0.0);
                const double wh  = atomicAdd(&g_acc[1 * ACC_STRIDE], 0.0);
                const double obj = atomicAdd(&g_acc[2 * ACC_STRIDE], 0.0);
                const double nob = atomicAdd(&g_acc[3 * ACC_STRIDE], 0.0);
                const double cls = atomicAdd(&g_acc[4 * ACC_STRIDE], 0.0);
                const double total = LAMBDA_COORD * (xy + wh) + obj
                                   + LAMBDA_NOOBJ * nob + LAMBDA_CLASS * cls;
                const double inv_bs = 1.0 / (double)BATCHN;
                out[0] = (float)(xy  * inv_bs);
                out[1] = (float)(wh  * inv_bs);
                out[2] = (float)(obj * inv_bs);
                out[3] = (float)(nob * inv_bs);
                out[4] = (float)(cls * inv_bs);
                out[5] = (float)(total * inv_bs);
                // Reset state for the next launch / graph replay.
                g_acc[0 * ACC_STRIDE] = 0.0;
                g_acc[1 * ACC_STRIDE] = 0.0;
                g_acc[2 * ACC_STRIDE] = 0.0;
                g_acc[3 * ACC_STRIDE] = 0.0;
                g_acc[4 * ACC_STRIDE] = 0.0;
                __threadfence();
                g_done = 0u;
            }
        }
    }
}

extern "C" void kernel_launch(void* const* d_in, const int* in_sizes, int n_in,
                              void* d_out, int out_size) {
    // pred is the big input (NCELLS*24 floats); target is NCELLS*4
    const float* pred = (const float*)d_in[0];
    const float* tgt  = (const float*)d_in[1];
    if (n_in >= 2 && in_sizes[0] < in_sizes[1]) {
        pred = (const float*)d_in[1];
        tgt  = (const float*)d_in[0];
    }

    loss_kernel<<<GRID, 256>>>(reinterpret_cast<const float4*>(pred),
                               reinterpret_cast<const float4*>(tgt),
                               (float*)d_out);
}

// round 17
// speedup vs baseline: 1.3251x; 1.0720x over previous
#include <cuda_runtime.h>
#include <cstdint>

// Problem constants
#define S2       100                   // S*S
#define NCH      24                    // 3*B + C
#define NCLS     21
#define BATCHN   32768
#define NCELLS   (BATCHN * S2)         // 3,276,800
#define GRID     3200
#define WPB      8                     // warps per block
#define WARPS_TOTAL (GRID * WPB)       // 25600
#define CHUNK    32                    // cells per warp-iteration (1 lane/cell)
#define CPW      (NCELLS / CHUNK / WARPS_TOTAL)  // 4 chunks per warp
#define SLOTS    (CHUNK * 6)           // 192 float4 per buffer

// Loss weights
#define LAMBDA_COORD 10.0
#define LAMBDA_NOOBJ 1.0
#define LAMBDA_CLASS 0.5

// log(w / SCALE) = log(w * INV_SCALE), SCALE = 6.5131/40
__device__ __constant__ float INV_SCALE = 40.0f / 6.5131f;

// Cross-block accumulators [xy, wh, obj, noobj, class], each on its own
// 128B line. Zero-initialized at module load; the finalizing block resets
// them after reading, so every launch / graph replay starts from zero.
#define ACC_STRIDE 16   // doubles per slot (128 B)
__device__ double g_acc[5 * ACC_STRIDE];     // static-init 0.0
__device__ unsigned int g_done;              // static-init 0

__device__ __forceinline__ float warp_reduce(float v) {
#pragma unroll
    for (int o = 16; o > 0; o >>= 1)
        v += __shfl_down_sync(0xffffffffu, v, o);
    return v;
}

__device__ __forceinline__ void cp_async16(uint32_t dst, const void* src) {
    asm volatile("cp.async.cg.shared.global [%0], [%1], 16;\n"
                 :: "r"(dst), "l"(src) : "memory");
}
__device__ __forceinline__ void cp_commit() {
    asm volatile("cp.async.commit_group;\n" ::: "memory");
}

__global__ __launch_bounds__(256, 4)
void loss_kernel(const float4* __restrict__ pred4,   // NCELLS*6 float4
                 const float4* __restrict__ tgt4,    // NCELLS float4
                 float* __restrict__ out) {
    // Per-warp double-buffered pred slices, cell-major float4 (slot = linear).
    // 8 warps x 2 bufs x 192 float4 x 16B = 49152 B (static 48KB exactly).
    __shared__ float4 s[WPB][2][SLOTS];

    const int tid  = threadIdx.x;
    const int lane = tid & 31;
    const int wid  = tid >> 5;

    const uint32_t sbase =
        (uint32_t)__cvta_generic_to_shared(&s[wid][0][0]) + lane * 16u;

    float lxy = 0.f, lwh = 0.f, lobj = 0.f, lnoobj = 0.f, lcls = 0.f;

    // ---- kick chunk 0 into buffer 0; target via register LDG ----
    int chunk = blockIdx.x * WPB + wid;
    {
        const float4* src = pred4 + (size_t)chunk * SLOTS + lane;
#pragma unroll
        for (int k = 0; k < 6; k++)
            cp_async16(sbase + k * 512u, src + k * 32);
        cp_commit();
    }
    float4 t = tgt4[chunk * CHUNK + lane];

#pragma unroll 1
    for (int it = 0; it < CPW; it++) {
        const float4 tc = t;
        const int nchunk = chunk + WARPS_TOTAL;

        if (it + 1 < CPW) {
            // issue next chunk into the other buffer, then wait for current
            t = tgt4[nchunk * CHUNK + lane];
            const float4* src = pred4 + (size_t)nchunk * SLOTS + lane;
            const uint32_t dst = sbase + (uint32_t)(((it + 1) & 1) * SLOTS) * 16u;
#pragma unroll
            for (int k = 0; k < 6; k++)
                cp_async16(dst + k * 512u, src + k * 32);
            cp_commit();
            asm volatile("cp.async.wait_group 1;\n" ::: "memory");
        } else {
            asm volatile("cp.async.wait_group 0;\n" ::: "memory");
        }
        __syncwarp();   // cross-lane visibility of async-filled buffer
        chunk = nchunk;

        // ---- read own cell (lane) : 6 x LDS.128, all 24 channels to regs ----
        const float4* sb = &s[wid][it & 1][lane * 6];
        const float4 q0 = sb[0];
        const float4 q1 = sb[1];
        const float4 q2 = sb[2];
        const float4 q3 = sb[3];
        const float4 q4 = sb[4];
        const float4 q5 = sb[5];

        const float sig_conf = 1.f / (1.f + __expf(-q0.z));

        if (tc.z > 0.f) {
            const float dc = sig_conf - tc.z;
            lobj += dc * dc;

            const float sig_x = 1.f / (1.f + __expf(-q0.x));
            const float dx = sig_x - tc.x;
            lxy += dx * dx;

            const float dw = q0.y - __logf(tc.y * INV_SCALE);
            lwh += dw * dw;

            if (tc.w > 0.f) {
                // channels 3..23 = cls0..cls20, register-resident
                const float cv[NCLS] = {
                    q0.w, q1.x, q1.y, q1.z, q1.w,
                    q2.x, q2.y, q2.z, q2.w,
                    q3.x, q3.y, q3.z, q3.w,
                    q4.x, q4.y, q4.z, q4.w,
                    q5.x, q5.y, q5.z, q5.w };
                float esum = 0.f, wsum = 0.f;
#pragma unroll
                for (int c = 0; c < NCLS; c++) {
                    const float e = __expf(cv[c]);
                    esum += e;
                    wsum += e * (1.0f + 0.5f * (float)c);
                }
                const float pred_mass = wsum / esum;
                const float diff = 10.f * (pred_mass + 1.f) / (tc.w + 1.f) - 10.f;
                const float ad = fabsf(diff);
                lcls += (ad < 1.f) ? 0.5f * diff * diff : (ad - 0.5f);
            }
        } else {
            lnoobj += sig_conf * sig_conf;   // target conf == 0
        }
        __syncwarp();   // all lanes done reading before buffer reuse
    }

    // ---- block reduction (reuse pred smem for the 5x8 partials) ----
    __syncthreads();
    float* rr = reinterpret_cast<float*>(&s[0][0][0]);   // [5][WPB]

    lxy    = warp_reduce(lxy);
    lwh    = warp_reduce(lwh);
    lobj   = warp_reduce(lobj);
    lnoobj = warp_reduce(lnoobj);
    lcls   = warp_reduce(lcls);

    if (lane == 0) {
        rr[0 * WPB + wid] = lxy;
        rr[1 * WPB + wid] = lwh;
        rr[2 * WPB + wid] = lobj;
        rr[3 * WPB + wid] = lnoobj;
        rr[4 * WPB + wid] = lcls;
    }
    __syncthreads();

    if (wid == 0) {
        float a0 = (lane < WPB) ? rr[0 * WPB + lane] : 0.f;
        float a1 = (lane < WPB) ? rr[1 * WPB + lane] : 0.f;
        float a2 = (lane < WPB) ? rr[2 * WPB + lane] : 0.f;
        float a3 = (lane < WPB) ? rr[3 * WPB + lane] : 0.f;
        float a4 = (lane < WPB) ? rr[4 * WPB + lane] : 0.f;
        a0 = warp_reduce(a0);
        a1 = warp_reduce(a1);
        a2 = warp_reduce(a2);
        a3 = warp_reduce(a3);
        a4 = warp_reduce(a4);

        if (lane == 0) {
            atomicAdd(&g_acc[0 * ACC_STRIDE], (double)a0);
            atomicAdd(&g_acc[1 * ACC_STRIDE], (double)a1);
            atomicAdd(&g_acc[2 * ACC_STRIDE], (double)a2);
            atomicAdd(&g_acc[3 * ACC_STRIDE], (double)a3);
            atomicAdd(&g_acc[4 * ACC_STRIDE], (double)a4);

            // ---- last-block-done finalize ----
            __threadfence();
            const unsigned int prev = atomicAdd(&g_done, 1u);
            if (prev == GRID - 1) {
                const double xy  = atomicAdd(&g_acc[0 * ACC_STRIDE], 0.0);
                const double wh  = atomicAdd(&g_acc[1 * ACC_STRIDE], 0.0);
                const double obj = atomicAdd(&g_acc[2 * ACC_STRIDE], 0.0);
                const double nob = atomicAdd(&g_acc[3 * ACC_STRIDE], 0.0);
                const double cls = atomicAdd(&g_acc[4 * ACC_STRIDE], 0.0);
                const double total = LAMBDA_COORD * (xy + wh) + obj
                                   + LAMBDA_NOOBJ * nob + LAMBDA_CLASS * cls;
                const double inv_bs = 1.0 / (double)BATCHN;
                out[0] = (float)(xy  * inv_bs);
                out[1] = (float)(wh  * inv_bs);
                out[2] = (float)(obj * inv_bs);
                out[3] = (float)(nob * inv_bs);
                out[4] = (float)(cls * inv_bs);
                out[5] = (float)(total * inv_bs);
                // Reset state for the next launch / graph replay.
                g_acc[0 * ACC_STRIDE] = 0.0;
                g_acc[1 * ACC_STRIDE] = 0.0;
                g_acc[2 * ACC_STRIDE] = 0.0;
                g_acc[3 * ACC_STRIDE] = 0.0;
                g_acc[4 * ACC_STRIDE] = 0.0;
                __threadfence();
                g_done = 0u;
            }
        }
    }
}

extern "C" void kernel_launch(void* const* d_in, const int* in_sizes, int n_in,
                              void* d_out, int out_size) {
    // pred is the big input (NCELLS*24 floats); target is NCELLS*4
    const float* pred = (const float*)d_in[0];
    const float* tgt  = (const float*)d_in[1];
    if (n_in >= 2 && in_sizes[0] < in_sizes[1]) {
        pred = (const float*)d_in[1];
        tgt  = (const float*)d_in[0];
    }

    loss_kernel<<<GRID, 256>>>(reinterpret_cast<const float4*>(pred),
                               reinterpret_cast<const float4*>(tgt),
                               (float*)d_out);
}